// round 11
// baseline (speedup 1.0000x reference)
#include <cuda_runtime.h>
#include <cstdint>

// Fixed dataset shape: state (2, NX, NY) fp32, x:(NX,), y:(NY,)
// R11: design held stable pending first successful bench (all prior rounds infra-failed).
#define MAX_NX 2048
#define MAX_NY 4096

// ---- coefficient tables -------------------------------------------------
// x-axis: per-row uniform -> packed float4 triples {a,b,c,0}
__device__ float4 g_cx1v[MAX_NX];
__device__ float4 g_cx2v[MAX_NX];
// y-axis: SoA component arrays (coalesced scalar loads AND float4-chunk loads)
__device__ float g_ay1[MAX_NY], g_by1[MAX_NY], g_cy1[MAX_NY];
__device__ float g_ay2[MAX_NY], g_by2[MAX_NY], g_cy2[MAX_NY];

// Derivative at index i uses f[im], f[im+1], f[im+2], im = clamp(i-1, 0, n-3).
// Edge-index coefficients reproduce the reference's one-sided stencils exactly.
__device__ __forceinline__ void coeffs_at(const float* __restrict__ g, int n, int i,
                                          float& a1, float& b1, float& cc1,
                                          float& a2, float& b2, float& cc2) {
    if (i == 0) {
        float hA = g[1] - g[0];
        float hB = g[2] - g[1];
        a1  = -(2.f * hA + hB) / (hA * (hA + hB));
        b1  =  (hA + hB) / (hA * hB);
        cc1 = -hA / (hB * (hA + hB));
        a2  =  2.f / (hA * (hA + hB));
        b2  = -2.f / (hA * hB);
        cc2 =  2.f / (hB * (hA + hB));
    } else if (i == n - 1) {
        float hC = g[n - 2] - g[n - 3];
        float hD = g[n - 1] - g[n - 2];
        a1  =  hD / (hC * (hC + hD));
        b1  = -(hC + hD) / (hC * hD);
        cc1 =  (hC + 2.f * hD) / (hD * (hC + hD));
        a2  =  2.f / (hC * (hC + hD));
        b2  = -2.f / (hC * hD);
        cc2 =  2.f / (hD * (hC + hD));
    } else {
        float h1 = g[i] - g[i - 1];
        float h2 = g[i + 1] - g[i];
        a1  = -h2 / (h1 * (h1 + h2));
        b1  = (h2 - h1) / (h1 * h2);
        cc1 = h1 / (h2 * (h1 + h2));
        a2  =  2.f / (h1 * (h1 + h2));
        b2  = -2.f / (h1 * h2);
        cc2 =  2.f / (h2 * (h1 + h2));
    }
}

__global__ void coeff_kernel_fused(const float* __restrict__ x, int nx,
                                   const float* __restrict__ y, int ny) {
    int t = blockIdx.x * blockDim.x + threadIdx.x;
    if (t < nx) {
        float a1, b1, c1, a2, b2, c2;
        coeffs_at(x, nx, t, a1, b1, c1, a2, b2, c2);
        g_cx1v[t] = make_float4(a1, b1, c1, 0.f);
        g_cx2v[t] = make_float4(a2, b2, c2, 0.f);
    } else if (t < nx + ny) {
        int i = t - nx;
        float a1, b1, c1, a2, b2, c2;
        coeffs_at(y, ny, i, a1, b1, c1, a2, b2, c2);
        g_ay1[i] = a1;  g_by1[i] = b1;  g_cy1[i] = c1;
        g_ay2[i] = a2;  g_by2[i] = b2;  g_cy2[i] = c2;
    }
}

__device__ __forceinline__ void ld4(float* d, const float* __restrict__ p) {
    float4 t = *reinterpret_cast<const float4*>(p);
    d[0] = t.x; d[1] = t.y; d[2] = t.z; d[3] = t.w;
}

// ---- vectorized RHS: each thread computes 4 consecutive j (float4 I/O) ----
// block (32,8): 128 j-columns x 8 rows per block; x-stencil rows reused in L1
// across the 8 row-threads. All global loads front-batched for MLP.
// Edge windows hand-verified: loEdge k=0 -> au[0..2] (jm=0); hiEdge k=3 ->
// au[1..3] (jm=ny-3); interior k windows match jm=j-1.
__global__ void __launch_bounds__(256, 2)
rhs_kernel_v4(const float* __restrict__ state, const float* __restrict__ mu_p,
              float* __restrict__ out, int nx, int ny) {
    int j0 = (blockIdx.x * 32 + threadIdx.x) * 4;
    int i  = blockIdx.y * 8 + threadIdx.y;
    if (j0 >= ny || i >= nx) return;

    const size_t plane = (size_t)nx * (size_t)ny;
    const float* __restrict__ u = state;
    const float* __restrict__ v = state + plane;

    int im = i - 1;
    if (im < 0) im = 0;
    if (im > nx - 3) im = nx - 3;

    const size_t rowi = (size_t)i * ny;
    const size_t row0 = (size_t)im * ny;
    const size_t row1 = row0 + ny;
    const size_t row2 = row1 + ny;

    // ---- front-batched loads (max MLP) ----
    float mu = __ldg(mu_p);

    // x-stencil rows (float4 per row per field)
    float xu0[4], xu1[4], xu2[4], xv0[4], xv1[4], xv2[4];
    ld4(xu0, u + row0 + j0);  ld4(xu1, u + row1 + j0);  ld4(xu2, u + row2 + j0);
    ld4(xv0, v + row0 + j0);  ld4(xv1, v + row1 + j0);  ld4(xv2, v + row2 + j0);

    // y-stencil: aligned center chunk + guarded edge scalars
    float au[4], av[4];
    ld4(au, u + rowi + j0);   ld4(av, v + rowi + j0);
    float fm1u = (j0 > 0)      ? u[rowi + j0 - 1] : 0.f;
    float fm1v = (j0 > 0)      ? v[rowi + j0 - 1] : 0.f;
    float fp4u = (j0 + 4 < ny) ? u[rowi + j0 + 4] : 0.f;
    float fp4v = (j0 + 4 < ny) ? v[rowi + j0 + 4] : 0.f;

    // y coefficients: float4 chunk per SoA table (perfectly coalesced)
    float ca1[4], cb1[4], cc1[4], ca2[4], cb2[4], cc2[4];
    ld4(ca1, g_ay1 + j0);  ld4(cb1, g_by1 + j0);  ld4(cc1, g_cy1 + j0);
    ld4(ca2, g_ay2 + j0);  ld4(cb2, g_by2 + j0);  ld4(cc2, g_cy2 + j0);

    // x coefficients (warp-uniform)
    float4 cx1 = g_cx1v[i];
    float4 cx2 = g_cx2v[i];

    const bool loEdge = (j0 == 0);
    const bool hiEdge = (j0 == ny - 4);

    float du4[4], dv4[4];

#pragma unroll
    for (int k = 0; k < 4; k++) {
        // y-window select (static per k; ternaries only at the two edge threads)
        float yu0, yu1, yu2, yv0, yv1, yv2;
        if (k == 0) {
            yu0 = loEdge ? au[0] : fm1u;  yu1 = loEdge ? au[1] : au[0];  yu2 = loEdge ? au[2] : au[1];
            yv0 = loEdge ? av[0] : fm1v;  yv1 = loEdge ? av[1] : av[0];  yv2 = loEdge ? av[2] : av[1];
        } else if (k == 1) {
            yu0 = au[0]; yu1 = au[1]; yu2 = au[2];
            yv0 = av[0]; yv1 = av[1]; yv2 = av[2];
        } else if (k == 2) {
            yu0 = au[1]; yu1 = au[2]; yu2 = au[3];
            yv0 = av[1]; yv1 = av[2]; yv2 = av[3];
        } else {
            yu0 = hiEdge ? au[1] : au[2];  yu1 = hiEdge ? au[2] : au[3];  yu2 = hiEdge ? au[3] : fp4u;
            yv0 = hiEdge ? av[1] : av[2];  yv1 = hiEdge ? av[2] : av[3];  yv2 = hiEdge ? av[3] : fp4v;
        }

        float d1y_u = ca1[k] * yu0 + cb1[k] * yu1 + cc1[k] * yu2;
        float d2y_u = ca2[k] * yu0 + cb2[k] * yu1 + cc2[k] * yu2;
        float d1y_v = ca1[k] * yv0 + cb1[k] * yv1 + cc1[k] * yv2;
        float d2y_v = ca2[k] * yv0 + cb2[k] * yv1 + cc2[k] * yv2;

        float d1x_u = cx1.x * xu0[k] + cx1.y * xu1[k] + cx1.z * xu2[k];
        float d2x_u = cx2.x * xu0[k] + cx2.y * xu1[k] + cx2.z * xu2[k];
        float d1x_v = cx1.x * xv0[k] + cx1.y * xv1[k] + cx1.z * xv2[k];
        float d2x_v = cx2.x * xv0[k] + cx2.y * xv1[k] + cx2.z * xv2[k];

        float u_c = au[k];
        float v_c = av[k];

        float du = mu * (d2y_u + d2x_u) - u_c * d1x_u - v_c * d1y_u + 0.01f;
        float dv = mu * (d2y_v + d2x_v) - u_c * d1x_v - v_c * d1y_v;

        int j = j0 + k;
        if (i == 0 || j == 0 || j == ny - 1) du = 0.0f;
        if (i == 0 || j == 0) dv = 0.0f;
        du4[k] = du;
        dv4[k] = dv;
    }

    *reinterpret_cast<float4*>(out + rowi + j0) =
        make_float4(du4[0], du4[1], du4[2], du4[3]);
    *reinterpret_cast<float4*>(out + plane + rowi + j0) =
        make_float4(dv4[0], dv4[1], dv4[2], dv4[3]);
}

// ---- scalar fallback (only used if ny % 4 != 0) ----
__global__ void __launch_bounds__(256)
rhs_kernel_scalar(const float* __restrict__ state, const float* __restrict__ mu_p,
                  float* __restrict__ out, int nx, int ny) {
    int j = blockIdx.x * 32 + threadIdx.x;
    int i = blockIdx.y * 8 + threadIdx.y;
    if (j >= ny || i >= nx) return;

    const size_t plane = (size_t)nx * (size_t)ny;
    const float* __restrict__ u = state;
    const float* __restrict__ v = state + plane;

    int im = i - 1;
    if (im < 0) im = 0;
    if (im > nx - 3) im = nx - 3;
    int jm = j - 1;
    if (jm < 0) jm = 0;
    if (jm > ny - 3) jm = ny - 3;

    const size_t rowi = (size_t)i * ny;
    const size_t row0 = (size_t)im * ny;
    const size_t row1 = row0 + ny;
    const size_t row2 = row1 + ny;

    float mu  = __ldg(mu_p);
    float ux0 = u[row0 + j], ux1 = u[row1 + j], ux2 = u[row2 + j];
    float vx0 = v[row0 + j], vx1 = v[row1 + j], vx2 = v[row2 + j];
    float uy0 = u[rowi + jm], uy1 = u[rowi + jm + 1], uy2 = u[rowi + jm + 2];
    float vy0 = v[rowi + jm], vy1 = v[rowi + jm + 1], vy2 = v[rowi + jm + 2];

    float4 cx1 = g_cx1v[i];
    float4 cx2 = g_cx2v[i];
    float ay1 = g_ay1[j], by1 = g_by1[j], cy1 = g_cy1[j];
    float ay2 = g_ay2[j], by2 = g_by2[j], cy2 = g_cy2[j];

    float d1x_u = cx1.x * ux0 + cx1.y * ux1 + cx1.z * ux2;
    float d2x_u = cx2.x * ux0 + cx2.y * ux1 + cx2.z * ux2;
    float d1y_u = ay1 * uy0 + by1 * uy1 + cy1 * uy2;
    float d2y_u = ay2 * uy0 + by2 * uy1 + cy2 * uy2;
    float d1x_v = cx1.x * vx0 + cx1.y * vx1 + cx1.z * vx2;
    float d2x_v = cx2.x * vx0 + cx2.y * vx1 + cx2.z * vx2;
    float d1y_v = ay1 * vy0 + by1 * vy1 + cy1 * vy2;
    float d2y_v = ay2 * vy0 + by2 * vy1 + cy2 * vy2;

    int k = j - jm;
    float u_c = (k == 0) ? uy0 : ((k == 1) ? uy1 : uy2);
    float v_c = (k == 0) ? vy0 : ((k == 1) ? vy1 : vy2);

    float du = mu * (d2y_u + d2x_u) - u_c * d1x_u - v_c * d1y_u + 0.01f;
    float dv = mu * (d2y_v + d2x_v) - u_c * d1x_v - v_c * d1y_v;

    if (i == 0 || j == 0 || j == ny - 1) du = 0.0f;
    if (i == 0 || j == 0) dv = 0.0f;

    out[rowi + j] = du;
    out[plane + rowi + j] = dv;
}

extern "C" void kernel_launch(void* const* d_in, const int* in_sizes, int n_in,
                              void* d_out, int out_size) {
    // metadata order: t, state, x, y, mu
    const float* state = (const float*)d_in[1];
    const float* x     = (const float*)d_in[2];
    const float* y     = (const float*)d_in[3];
    const float* mu    = (const float*)d_in[4];
    float* out = (float*)d_out;

    int nx = in_sizes[2];
    int ny = in_sizes[3];

    int nc = nx + ny;
    coeff_kernel_fused<<<(nc + 255) / 256, 256>>>(x, nx, y, ny);

    if ((ny & 3) == 0) {
        dim3 block(32, 8, 1);
        dim3 grid((ny / 4 + 31) / 32, (nx + 7) / 8, 1);
        rhs_kernel_v4<<<grid, block>>>(state, mu, out, nx, ny);
    } else {
        dim3 block(32, 8, 1);
        dim3 grid((ny + 31) / 32, (nx + 7) / 8, 1);
        rhs_kernel_scalar<<<grid, block>>>(state, mu, out, nx, ny);
    }
}

// round 16
// speedup vs baseline: 1.0156x; 1.0156x over previous
#include <cuda_runtime.h>
#include <cstdint>

// Fixed dataset shape: state (2, NX, NY) fp32, x:(NX,), y:(NY,)
// R16: resubmit of occupancy fix (infra failed 4x before it could bench).
// R11 profile: 86 regs, occ 20.5%, all pipes <50% => latency-bound.
#define MAX_NX 2048
#define MAX_NY 4096

// ---- coefficient tables -------------------------------------------------
__device__ float4 g_cx1v[MAX_NX];
__device__ float4 g_cx2v[MAX_NX];
__device__ float g_ay1[MAX_NY], g_by1[MAX_NY], g_cy1[MAX_NY];
__device__ float g_ay2[MAX_NY], g_by2[MAX_NY], g_cy2[MAX_NY];

// Derivative at index i uses f[im], f[im+1], f[im+2], im = clamp(i-1, 0, n-3).
__device__ __forceinline__ void coeffs_at(const float* __restrict__ g, int n, int i,
                                          float& a1, float& b1, float& cc1,
                                          float& a2, float& b2, float& cc2) {
    if (i == 0) {
        float hA = g[1] - g[0];
        float hB = g[2] - g[1];
        a1  = -(2.f * hA + hB) / (hA * (hA + hB));
        b1  =  (hA + hB) / (hA * hB);
        cc1 = -hA / (hB * (hA + hB));
        a2  =  2.f / (hA * (hA + hB));
        b2  = -2.f / (hA * hB);
        cc2 =  2.f / (hB * (hA + hB));
    } else if (i == n - 1) {
        float hC = g[n - 2] - g[n - 3];
        float hD = g[n - 1] - g[n - 2];
        a1  =  hD / (hC * (hC + hD));
        b1  = -(hC + hD) / (hC * hD);
        cc1 =  (hC + 2.f * hD) / (hD * (hC + hD));
        a2  =  2.f / (hC * (hC + hD));
        b2  = -2.f / (hC * hD);
        cc2 =  2.f / (hD * (hC + hD));
    } else {
        float h1 = g[i] - g[i - 1];
        float h2 = g[i + 1] - g[i];
        a1  = -h2 / (h1 * (h1 + h2));
        b1  = (h2 - h1) / (h1 * h2);
        cc1 = h1 / (h2 * (h1 + h2));
        a2  =  2.f / (h1 * (h1 + h2));
        b2  = -2.f / (h1 * h2);
        cc2 =  2.f / (h2 * (h1 + h2));
    }
}

__global__ void coeff_kernel_fused(const float* __restrict__ x, int nx,
                                   const float* __restrict__ y, int ny) {
    int t = blockIdx.x * blockDim.x + threadIdx.x;
    if (t < nx) {
        float a1, b1, c1, a2, b2, c2;
        coeffs_at(x, nx, t, a1, b1, c1, a2, b2, c2);
        g_cx1v[t] = make_float4(a1, b1, c1, 0.f);
        g_cx2v[t] = make_float4(a2, b2, c2, 0.f);
    } else if (t < nx + ny) {
        int i = t - nx;
        float a1, b1, c1, a2, b2, c2;
        coeffs_at(y, ny, i, a1, b1, c1, a2, b2, c2);
        g_ay1[i] = a1;  g_by1[i] = b1;  g_cy1[i] = c1;
        g_ay2[i] = a2;  g_by2[i] = b2;  g_cy2[i] = c2;
    }
}

__device__ __forceinline__ void ld2(float* d, const float* __restrict__ p) {
    float2 t = *reinterpret_cast<const float2*>(p);
    d[0] = t.x; d[1] = t.y;
}

// ---- x2-vectorized RHS: each thread computes 2 consecutive j (float2 I/O) ----
// block (32,8): 64 j-columns x 8 rows per block; x-stencil rows reused in L1.
// __launch_bounds__(256, 4) caps regs at 64 -> 4 blocks/SM -> ~50% occupancy.
// y-windows: interior k=0 -> (f[j0-1],f[j0],f[j0+1]); interior k=1 ->
// (f[j0],f[j0+1],f[j0+2]); loEdge k=0 -> jm=0 window; hiEdge k=1 -> jm=ny-3 window.
__global__ void __launch_bounds__(256, 4)
rhs_kernel_v2(const float* __restrict__ state, const float* __restrict__ mu_p,
              float* __restrict__ out, int nx, int ny) {
    int j0 = (blockIdx.x * 32 + threadIdx.x) * 2;
    int i  = blockIdx.y * 8 + threadIdx.y;
    if (j0 >= ny || i >= nx) return;

    const size_t plane = (size_t)nx * (size_t)ny;
    const float* __restrict__ u = state;
    const float* __restrict__ v = state + plane;

    int im = i - 1;
    if (im < 0) im = 0;
    if (im > nx - 3) im = nx - 3;

    const size_t rowi = (size_t)i * ny;
    const size_t row0 = (size_t)im * ny;
    const size_t row1 = row0 + ny;
    const size_t row2 = row1 + ny;

    // ---- front-batched loads (max MLP) ----
    float mu = __ldg(mu_p);

    float xu0[2], xu1[2], xu2[2], xv0[2], xv1[2], xv2[2];
    ld2(xu0, u + row0 + j0);  ld2(xu1, u + row1 + j0);  ld2(xu2, u + row2 + j0);
    ld2(xv0, v + row0 + j0);  ld2(xv1, v + row1 + j0);  ld2(xv2, v + row2 + j0);

    float au[2], av[2];
    ld2(au, u + rowi + j0);   ld2(av, v + rowi + j0);
    float fm1u = (j0 > 0)      ? u[rowi + j0 - 1] : 0.f;
    float fm1v = (j0 > 0)      ? v[rowi + j0 - 1] : 0.f;
    float fp2u = (j0 + 2 < ny) ? u[rowi + j0 + 2] : 0.f;
    float fp2v = (j0 + 2 < ny) ? v[rowi + j0 + 2] : 0.f;

    float ca1[2], cb1[2], cc1[2], ca2[2], cb2[2], cc2[2];
    ld2(ca1, g_ay1 + j0);  ld2(cb1, g_by1 + j0);  ld2(cc1, g_cy1 + j0);
    ld2(ca2, g_ay2 + j0);  ld2(cb2, g_by2 + j0);  ld2(cc2, g_cy2 + j0);

    float4 cx1 = g_cx1v[i];
    float4 cx2 = g_cx2v[i];

    const bool loEdge = (j0 == 0);
    const bool hiEdge = (j0 == ny - 2);

    float du2[2], dv2[2];

#pragma unroll
    for (int k = 0; k < 2; k++) {
        float yu0, yu1, yu2, yv0, yv1, yv2;
        if (k == 0) {
            yu0 = loEdge ? au[0] : fm1u;  yu1 = loEdge ? au[1] : au[0];  yu2 = loEdge ? fp2u : au[1];
            yv0 = loEdge ? av[0] : fm1v;  yv1 = loEdge ? av[1] : av[0];  yv2 = loEdge ? fp2v : av[1];
        } else {
            yu0 = hiEdge ? fm1u : au[0];  yu1 = hiEdge ? au[0] : au[1];  yu2 = hiEdge ? au[1] : fp2u;
            yv0 = hiEdge ? fm1v : av[0];  yv1 = hiEdge ? av[0] : av[1];  yv2 = hiEdge ? av[1] : fp2v;
        }

        float d1y_u = ca1[k] * yu0 + cb1[k] * yu1 + cc1[k] * yu2;
        float d2y_u = ca2[k] * yu0 + cb2[k] * yu1 + cc2[k] * yu2;
        float d1y_v = ca1[k] * yv0 + cb1[k] * yv1 + cc1[k] * yv2;
        float d2y_v = ca2[k] * yv0 + cb2[k] * yv1 + cc2[k] * yv2;

        float d1x_u = cx1.x * xu0[k] + cx1.y * xu1[k] + cx1.z * xu2[k];
        float d2x_u = cx2.x * xu0[k] + cx2.y * xu1[k] + cx2.z * xu2[k];
        float d1x_v = cx1.x * xv0[k] + cx1.y * xv1[k] + cx1.z * xv2[k];
        float d2x_v = cx2.x * xv0[k] + cx2.y * xv1[k] + cx2.z * xv2[k];

        float u_c = au[k];
        float v_c = av[k];

        float du = mu * (d2y_u + d2x_u) - u_c * d1x_u - v_c * d1y_u + 0.01f;
        float dv = mu * (d2y_v + d2x_v) - u_c * d1x_v - v_c * d1y_v;

        int j = j0 + k;
        if (i == 0 || j == 0 || j == ny - 1) du = 0.0f;
        if (i == 0 || j == 0) dv = 0.0f;
        du2[k] = du;
        dv2[k] = dv;
    }

    *reinterpret_cast<float2*>(out + rowi + j0) = make_float2(du2[0], du2[1]);
    *reinterpret_cast<float2*>(out + plane + rowi + j0) = make_float2(dv2[0], dv2[1]);
}

// ---- scalar fallback (only used if ny % 2 != 0) ----
__global__ void __launch_bounds__(256)
rhs_kernel_scalar(const float* __restrict__ state, const float* __restrict__ mu_p,
                  float* __restrict__ out, int nx, int ny) {
    int j = blockIdx.x * 32 + threadIdx.x;
    int i = blockIdx.y * 8 + threadIdx.y;
    if (j >= ny || i >= nx) return;

    const size_t plane = (size_t)nx * (size_t)ny;
    const float* __restrict__ u = state;
    const float* __restrict__ v = state + plane;

    int im = i - 1;
    if (im < 0) im = 0;
    if (im > nx - 3) im = nx - 3;
    int jm = j - 1;
    if (jm < 0) jm = 0;
    if (jm > ny - 3) jm = ny - 3;

    const size_t rowi = (size_t)i * ny;
    const size_t row0 = (size_t)im * ny;
    const size_t row1 = row0 + ny;
    const size_t row2 = row1 + ny;

    float mu  = __ldg(mu_p);
    float ux0 = u[row0 + j], ux1 = u[row1 + j], ux2 = u[row2 + j];
    float vx0 = v[row0 + j], vx1 = v[row1 + j], vx2 = v[row2 + j];
    float uy0 = u[rowi + jm], uy1 = u[rowi + jm + 1], uy2 = u[rowi + jm + 2];
    float vy0 = v[rowi + jm], vy1 = v[rowi + jm + 1], vy2 = v[rowi + jm + 2];

    float4 cx1 = g_cx1v[i];
    float4 cx2 = g_cx2v[i];
    float ay1 = g_ay1[j], by1 = g_by1[j], cy1 = g_cy1[j];
    float ay2 = g_ay2[j], by2 = g_by2[j], cy2 = g_cy2[j];

    float d1x_u = cx1.x * ux0 + cx1.y * ux1 + cx1.z * ux2;
    float d2x_u = cx2.x * ux0 + cx2.y * ux1 + cx2.z * ux2;
    float d1y_u = ay1 * uy0 + by1 * uy1 + cy1 * uy2;
    float d2y_u = ay2 * uy0 + by2 * uy1 + cy2 * uy2;
    float d1x_v = cx1.x * vx0 + cx1.y * vx1 + cx1.z * vx2;
    float d2x_v = cx2.x * vx0 + cx2.y * vx1 + cx2.z * vx2;
    float d1y_v = ay1 * vy0 + by1 * vy1 + cy1 * vy2;
    float d2y_v = ay2 * vy0 + by2 * vy1 + cy2 * vy2;

    int k = j - jm;
    float u_c = (k == 0) ? uy0 : ((k == 1) ? uy1 : uy2);
    float v_c = (k == 0) ? vy0 : ((k == 1) ? vy1 : vy2);

    float du = mu * (d2y_u + d2x_u) - u_c * d1x_u - v_c * d1y_u + 0.01f;
    float dv = mu * (d2y_v + d2x_v) - u_c * d1x_v - v_c * d1y_v;

    if (i == 0 || j == 0 || j == ny - 1) du = 0.0f;
    if (i == 0 || j == 0) dv = 0.0f;

    out[rowi + j] = du;
    out[plane + rowi + j] = dv;
}

extern "C" void kernel_launch(void* const* d_in, const int* in_sizes, int n_in,
                              void* d_out, int out_size) {
    // metadata order: t, state, x, y, mu
    const float* state = (const float*)d_in[1];
    const float* x     = (const float*)d_in[2];
    const float* y     = (const float*)d_in[3];
    const float* mu    = (const float*)d_in[4];
    float* out = (float*)d_out;

    int nx = in_sizes[2];
    int ny = in_sizes[3];

    int nc = nx + ny;
    coeff_kernel_fused<<<(nc + 255) / 256, 256>>>(x, nx, y, ny);

    if ((ny & 1) == 0) {
        dim3 block(32, 8, 1);
        dim3 grid((ny / 2 + 31) / 32, (nx + 7) / 8, 1);
        rhs_kernel_v2<<<grid, block>>>(state, mu, out, nx, ny);
    } else {
        dim3 block(32, 8, 1);
        dim3 grid((ny + 31) / 32, (nx + 7) / 8, 1);
        rhs_kernel_scalar<<<grid, block>>>(state, mu, out, nx, ny);
    }
}

// round 17
// speedup vs baseline: 1.1856x; 1.1673x over previous
#include <cuda_runtime.h>
#include <cstdint>

// Fixed dataset shape: state (2, NX, NY) fp32, x:(NX,), y:(NY,)
// R17: v4 (low-instruction) + 32-bit indexing (ALU was 43.6%) + (256,3) occupancy.
// Measured: v4@occ20.5% -> 42.1us (17.2 inst-units); v2@occ40.4% -> 39.7us (24.2 units).
#define MAX_NX 2048
#define MAX_NY 4096

// ---- coefficient tables -------------------------------------------------
__device__ float4 g_cx1v[MAX_NX];
__device__ float4 g_cx2v[MAX_NX];
__device__ float g_ay1[MAX_NY], g_by1[MAX_NY], g_cy1[MAX_NY];
__device__ float g_ay2[MAX_NY], g_by2[MAX_NY], g_cy2[MAX_NY];

// Derivative at index i uses f[im], f[im+1], f[im+2], im = clamp(i-1, 0, n-3).
__device__ __forceinline__ void coeffs_at(const float* __restrict__ g, int n, int i,
                                          float& a1, float& b1, float& cc1,
                                          float& a2, float& b2, float& cc2) {
    if (i == 0) {
        float hA = g[1] - g[0];
        float hB = g[2] - g[1];
        a1  = -(2.f * hA + hB) / (hA * (hA + hB));
        b1  =  (hA + hB) / (hA * hB);
        cc1 = -hA / (hB * (hA + hB));
        a2  =  2.f / (hA * (hA + hB));
        b2  = -2.f / (hA * hB);
        cc2 =  2.f / (hB * (hA + hB));
    } else if (i == n - 1) {
        float hC = g[n - 2] - g[n - 3];
        float hD = g[n - 1] - g[n - 2];
        a1  =  hD / (hC * (hC + hD));
        b1  = -(hC + hD) / (hC * hD);
        cc1 =  (hC + 2.f * hD) / (hD * (hC + hD));
        a2  =  2.f / (hC * (hC + hD));
        b2  = -2.f / (hC * hD);
        cc2 =  2.f / (hD * (hC + hD));
    } else {
        float h1 = g[i] - g[i - 1];
        float h2 = g[i + 1] - g[i];
        a1  = -h2 / (h1 * (h1 + h2));
        b1  = (h2 - h1) / (h1 * h2);
        cc1 = h1 / (h2 * (h1 + h2));
        a2  =  2.f / (h1 * (h1 + h2));
        b2  = -2.f / (h1 * h2);
        cc2 =  2.f / (h2 * (h1 + h2));
    }
}

__global__ void coeff_kernel_fused(const float* __restrict__ x, int nx,
                                   const float* __restrict__ y, int ny) {
    int t = blockIdx.x * blockDim.x + threadIdx.x;
    if (t < nx) {
        float a1, b1, c1, a2, b2, c2;
        coeffs_at(x, nx, t, a1, b1, c1, a2, b2, c2);
        g_cx1v[t] = make_float4(a1, b1, c1, 0.f);
        g_cx2v[t] = make_float4(a2, b2, c2, 0.f);
    } else if (t < nx + ny) {
        int i = t - nx;
        float a1, b1, c1, a2, b2, c2;
        coeffs_at(y, ny, i, a1, b1, c1, a2, b2, c2);
        g_ay1[i] = a1;  g_by1[i] = b1;  g_cy1[i] = c1;
        g_ay2[i] = a2;  g_by2[i] = b2;  g_cy2[i] = c2;
    }
}

__device__ __forceinline__ void ld4(float* d, const float* __restrict__ p) {
    float4 t = *reinterpret_cast<const float4*>(p);
    d[0] = t.x; d[1] = t.y; d[2] = t.z; d[3] = t.w;
}

// ---- x4-vectorized RHS, 32-bit indexing, (256,3) ----
// Each thread computes 4 consecutive j (float4 I/O). All offsets are 32-bit
// unsigned (2*nx*ny = 16M < 2^31) to kill the 64-bit IMAD addressing chains
// that showed up as alu=43.6% in the R16 profile.
__global__ void __launch_bounds__(256, 3)
rhs_kernel_v4(const float* __restrict__ state, const float* __restrict__ mu_p,
              float* __restrict__ out, int nx, int ny) {
    int j0 = (blockIdx.x * 32 + threadIdx.x) * 4;
    int i  = blockIdx.y * 8 + threadIdx.y;
    if (j0 >= ny || i >= nx) return;

    const unsigned plane = (unsigned)nx * (unsigned)ny;
    const float* __restrict__ u = state;
    const float* __restrict__ v = state + plane;

    int im = i - 1;
    if (im < 0) im = 0;
    if (im > nx - 3) im = nx - 3;

    const unsigned rowi = (unsigned)i * (unsigned)ny + (unsigned)j0;
    const unsigned row0 = (unsigned)im * (unsigned)ny + (unsigned)j0;
    const unsigned row1 = row0 + (unsigned)ny;
    const unsigned row2 = row1 + (unsigned)ny;

    // ---- front-batched loads (max MLP) ----
    float mu = __ldg(mu_p);

    float xu0[4], xu1[4], xu2[4], xv0[4], xv1[4], xv2[4];
    ld4(xu0, u + row0);  ld4(xu1, u + row1);  ld4(xu2, u + row2);
    ld4(xv0, v + row0);  ld4(xv1, v + row1);  ld4(xv2, v + row2);

    float au[4], av[4];
    ld4(au, u + rowi);   ld4(av, v + rowi);
    float fm1u = (j0 > 0)      ? u[rowi - 1] : 0.f;
    float fm1v = (j0 > 0)      ? v[rowi - 1] : 0.f;
    float fp4u = (j0 + 4 < ny) ? u[rowi + 4] : 0.f;
    float fp4v = (j0 + 4 < ny) ? v[rowi + 4] : 0.f;

    float ca1[4], cb1[4], cc1[4], ca2[4], cb2[4], cc2[4];
    ld4(ca1, g_ay1 + j0);  ld4(cb1, g_by1 + j0);  ld4(cc1, g_cy1 + j0);
    ld4(ca2, g_ay2 + j0);  ld4(cb2, g_by2 + j0);  ld4(cc2, g_cy2 + j0);

    float4 cx1 = g_cx1v[i];
    float4 cx2 = g_cx2v[i];

    const bool loEdge = (j0 == 0);
    const bool hiEdge = (j0 == ny - 4);

    float du4[4], dv4[4];

#pragma unroll
    for (int k = 0; k < 4; k++) {
        float yu0, yu1, yu2, yv0, yv1, yv2;
        if (k == 0) {
            yu0 = loEdge ? au[0] : fm1u;  yu1 = loEdge ? au[1] : au[0];  yu2 = loEdge ? au[2] : au[1];
            yv0 = loEdge ? av[0] : fm1v;  yv1 = loEdge ? av[1] : av[0];  yv2 = loEdge ? av[2] : av[1];
        } else if (k == 1) {
            yu0 = au[0]; yu1 = au[1]; yu2 = au[2];
            yv0 = av[0]; yv1 = av[1]; yv2 = av[2];
        } else if (k == 2) {
            yu0 = au[1]; yu1 = au[2]; yu2 = au[3];
            yv0 = av[1]; yv1 = av[2]; yv2 = av[3];
        } else {
            yu0 = hiEdge ? au[1] : au[2];  yu1 = hiEdge ? au[2] : au[3];  yu2 = hiEdge ? au[3] : fp4u;
            yv0 = hiEdge ? av[1] : av[2];  yv1 = hiEdge ? av[2] : av[3];  yv2 = hiEdge ? av[3] : fp4v;
        }

        float d1y_u = ca1[k] * yu0 + cb1[k] * yu1 + cc1[k] * yu2;
        float d2y_u = ca2[k] * yu0 + cb2[k] * yu1 + cc2[k] * yu2;
        float d1y_v = ca1[k] * yv0 + cb1[k] * yv1 + cc1[k] * yv2;
        float d2y_v = ca2[k] * yv0 + cb2[k] * yv1 + cc2[k] * yv2;

        float d1x_u = cx1.x * xu0[k] + cx1.y * xu1[k] + cx1.z * xu2[k];
        float d2x_u = cx2.x * xu0[k] + cx2.y * xu1[k] + cx2.z * xu2[k];
        float d1x_v = cx1.x * xv0[k] + cx1.y * xv1[k] + cx1.z * xv2[k];
        float d2x_v = cx2.x * xv0[k] + cx2.y * xv1[k] + cx2.z * xv2[k];

        float u_c = au[k];
        float v_c = av[k];

        float du = mu * (d2y_u + d2x_u) - u_c * d1x_u - v_c * d1y_u + 0.01f;
        float dv = mu * (d2y_v + d2x_v) - u_c * d1x_v - v_c * d1y_v;

        int j = j0 + k;
        if (i == 0 || j == 0 || j == ny - 1) du = 0.0f;
        if (i == 0 || j == 0) dv = 0.0f;
        du4[k] = du;
        dv4[k] = dv;
    }

    *reinterpret_cast<float4*>(out + rowi) =
        make_float4(du4[0], du4[1], du4[2], du4[3]);
    *reinterpret_cast<float4*>(out + plane + rowi) =
        make_float4(dv4[0], dv4[1], dv4[2], dv4[3]);
}

// ---- scalar fallback (only used if ny % 4 != 0) ----
__global__ void __launch_bounds__(256)
rhs_kernel_scalar(const float* __restrict__ state, const float* __restrict__ mu_p,
                  float* __restrict__ out, int nx, int ny) {
    int j = blockIdx.x * 32 + threadIdx.x;
    int i = blockIdx.y * 8 + threadIdx.y;
    if (j >= ny || i >= nx) return;

    const unsigned plane = (unsigned)nx * (unsigned)ny;
    const float* __restrict__ u = state;
    const float* __restrict__ v = state + plane;

    int im = i - 1;
    if (im < 0) im = 0;
    if (im > nx - 3) im = nx - 3;
    int jm = j - 1;
    if (jm < 0) jm = 0;
    if (jm > ny - 3) jm = ny - 3;

    const unsigned rowi = (unsigned)i * (unsigned)ny;
    const unsigned row0 = (unsigned)im * (unsigned)ny;
    const unsigned row1 = row0 + (unsigned)ny;
    const unsigned row2 = row1 + (unsigned)ny;

    float mu  = __ldg(mu_p);
    float ux0 = u[row0 + j], ux1 = u[row1 + j], ux2 = u[row2 + j];
    float vx0 = v[row0 + j], vx1 = v[row1 + j], vx2 = v[row2 + j];
    float uy0 = u[rowi + jm], uy1 = u[rowi + jm + 1], uy2 = u[rowi + jm + 2];
    float vy0 = v[rowi + jm], vy1 = v[rowi + jm + 1], vy2 = v[rowi + jm + 2];

    float4 cx1 = g_cx1v[i];
    float4 cx2 = g_cx2v[i];
    float ay1 = g_ay1[j], by1 = g_by1[j], cy1 = g_cy1[j];
    float ay2 = g_ay2[j], by2 = g_by2[j], cy2 = g_cy2[j];

    float d1x_u = cx1.x * ux0 + cx1.y * ux1 + cx1.z * ux2;
    float d2x_u = cx2.x * ux0 + cx2.y * ux1 + cx2.z * ux2;
    float d1y_u = ay1 * uy0 + by1 * uy1 + cy1 * uy2;
    float d2y_u = ay2 * uy0 + by2 * uy1 + cy2 * uy2;
    float d1x_v = cx1.x * vx0 + cx1.y * vx1 + cx1.z * vx2;
    float d2x_v = cx2.x * vx0 + cx2.y * vx1 + cx2.z * vx2;
    float d1y_v = ay1 * vy0 + by1 * vy1 + cy1 * vy2;
    float d2y_v = ay2 * vy0 + by2 * vy1 + cy2 * vy2;

    int k = j - jm;
    float u_c = (k == 0) ? uy0 : ((k == 1) ? uy1 : uy2);
    float v_c = (k == 0) ? vy0 : ((k == 1) ? vy1 : vy2);

    float du = mu * (d2y_u + d2x_u) - u_c * d1x_u - v_c * d1y_u + 0.01f;
    float dv = mu * (d2y_v + d2x_v) - u_c * d1x_v - v_c * d1y_v;

    if (i == 0 || j == 0 || j == ny - 1) du = 0.0f;
    if (i == 0 || j == 0) dv = 0.0f;

    out[rowi + j] = du;
    out[plane + rowi + j] = dv;
}

extern "C" void kernel_launch(void* const* d_in, const int* in_sizes, int n_in,
                              void* d_out, int out_size) {
    // metadata order: t, state, x, y, mu
    const float* state = (const float*)d_in[1];
    const float* x     = (const float*)d_in[2];
    const float* y     = (const float*)d_in[3];
    const float* mu    = (const float*)d_in[4];
    float* out = (float*)d_out;

    int nx = in_sizes[2];
    int ny = in_sizes[3];

    int nc = nx + ny;
    coeff_kernel_fused<<<(nc + 255) / 256, 256>>>(x, nx, y, ny);

    if ((ny & 3) == 0) {
        dim3 block(32, 8, 1);
        dim3 grid((ny / 4 + 31) / 32, (nx + 7) / 8, 1);
        rhs_kernel_v4<<<grid, block>>>(state, mu, out, nx, ny);
    } else {
        dim3 block(32, 8, 1);
        dim3 grid((ny + 31) / 32, (nx + 7) / 8, 1);
        rhs_kernel_scalar<<<grid, block>>>(state, mu, out, nx, ny);
    }
}